// round 11
// baseline (speedup 1.0000x reference)
#include <cuda_runtime.h>
#include <cuda_bf16.h>

#define T_SEQ   256
#define HID     128
#define BATCH   1024
#define VOCABN  60
#define NCTA    152

#define FMA2(acc, a, b) \
    asm("fma.rn.f32x2 %0, %1, %2, %0;" : "+l"(acc) : "l"(a), "l"(b))
#define ADD2(dst, a, b) \
    asm("add.rn.f32x2 %0, %1, %2;" : "=l"(dst) : "l"(a), "l"(b))
#define UNPACK2(lo, hi, v) \
    asm("mov.b64 {%0,%1}, %2;" : "=f"(lo), "=f"(hi) : "l"(v))

__device__ __forceinline__ float tanh_fast(float z) {
    float e = __expf(2.0f * z);
    return 1.0f - __fdividef(2.0f, e + 1.0f);
}

// 2-output x 32-k partial dot, chunked to keep live regs low.
// src = 8 ulonglong2 (32 floats); w[0..15] = row0 chunk, w[16..31] = row1 chunk.
__device__ __forceinline__ void dot2(
    const ulonglong2* __restrict__ src, const unsigned long long* w,
    float& s0, float& s1)
{
    unsigned long long A0 = 0ull, A1 = 0ull, A2 = 0ull, A3 = 0ull;
#pragma unroll
    for (int half = 0; half < 2; half++) {
        ulonglong2 v0 = src[half*4 + 0];
        ulonglong2 v1 = src[half*4 + 1];
        ulonglong2 v2 = src[half*4 + 2];
        ulonglong2 v3 = src[half*4 + 3];
        const unsigned long long* w0 = w + half * 8;
        const unsigned long long* w1 = w + 16 + half * 8;
        FMA2(A0, w0[0], v0.x); FMA2(A1, w0[1], v0.y);
        FMA2(A2, w1[0], v0.x); FMA2(A3, w1[1], v0.y);
        FMA2(A0, w0[2], v1.x); FMA2(A1, w0[3], v1.y);
        FMA2(A2, w1[2], v1.x); FMA2(A3, w1[3], v1.y);
        FMA2(A0, w0[4], v2.x); FMA2(A1, w0[5], v2.y);
        FMA2(A2, w1[4], v2.x); FMA2(A3, w1[5], v2.y);
        FMA2(A0, w0[6], v3.x); FMA2(A1, w0[7], v3.y);
        FMA2(A2, w1[6], v3.x); FMA2(A3, w1[7], v3.y);
    }
    float lo, hi;
    ADD2(A0, A0, A1); UNPACK2(lo, hi, A0); s0 = lo + hi;
    ADD2(A2, A2, A3); UNPACK2(lo, hi, A2); s1 = lo + hi;
}

// load rows {j2, j2+64} k-chunk kq of a 128x128 row-major matrix into 32 ull
__device__ __forceinline__ void load_w2(
    const float* __restrict__ Wsrc, int j2, int kq, unsigned long long* w)
{
#pragma unroll
    for (int r = 0; r < 2; r++) {
        const ulonglong2* Wq =
            reinterpret_cast<const ulonglong2*>(Wsrc) + (size_t)(j2 + 64*r) * 32 + kq * 8;
#pragma unroll
        for (int i = 0; i < 8; i++) {
            ulonglong2 t = Wq[i];
            w[r*16 + 2*i]     = t.x;
            w[r*16 + 2*i + 1] = t.y;
        }
    }
}

// ============ single fused kernel: sort + P + RNN + FC ============
// 152 CTAs x 512 threads (2 groups of 256; 4 warps/SMSP for latency hiding).
// Deterministic counting sort -> identical perm everywhere. Dual schedule as
// R10 (makespan ~281 steps). Thread (j2,kq) owns outputs {j2,j2+64} x 32-k
// chunk: 32 ull weight regs, 8 LDS.128/slot (conflict-free chunk layout),
// quad shfl-reduce. shP skew (stride 132) kills base-load bank conflicts.
__global__ __launch_bounds__(512, 1) void rnn_all(
    const int* __restrict__ x, const int* __restrict__ lengths,
    const float* __restrict__ W_hh,
    const float* __restrict__ emb, const float* __restrict__ W_ih,
    const float* __restrict__ W_fc, const float* __restrict__ b_fc,
    float* __restrict__ out)
{
    __shared__ __align__(16) unsigned char raw[34816];
    __shared__ __align__(16) float shH[2][2][2][144];   // [g][slot][buf][4 chunks x 36]

    unsigned short* hist = (unsigned short*)raw;            // [32][256]
    int*            tot  = (int*)(raw + 16384);             // [256]
    int*            bse  = (int*)(raw + 17408);             // [256]
    unsigned short* perm = (unsigned short*)(raw + 18432);  // [1024]
    float*          shP  = (float*)raw;                     // [60][132] skewed
    unsigned char*  stok = raw + 31680;                     // [4][256]
    float*          sret = (float*)(raw + 32704);           // [4][128]

    int tid  = threadIdx.x;
    int g    = tid >> 8;         // group 0/1
    int u    = tid & 255;
    int kq   = u & 3;            // k-chunk
    int j2   = u >> 2;           // 0..63
    int jown = j2 + 64 * (kq & 1);
    int jskew = jown + (jown >> 5);                 // shP skewed index
    int stskew = ((jown >> 5) * 36) + (jown & 31);  // shH chunk index
    int lane = tid & 31;
    int wrp  = tid >> 5;         // 0..15
    int c    = blockIdx.x;

    // ---------- deterministic counting sort (no atomics) ----------
    for (int i = tid; i < 8192; i += 512) hist[i] = 0;
    __syncthreads();
    int myintra[2], mylen[2];
#pragma unroll
    for (int bi = 0; bi < 2; bi++) {
        int b = wrp + bi * 16;               // 32 blocks of 32 rows
        int r = b * 32 + lane;
        int l = lengths[r] - 1;
        unsigned mask = __match_any_sync(0xffffffffu, l);
        int intra = __popc(mask & ((1u << lane) - 1u));
        if (intra == 0) hist[b * 256 + l] = (unsigned short)__popc(mask);
        myintra[bi] = intra; mylen[bi] = l;
    }
    __syncthreads();
    if (tid < 256) {    // per-bin serial scan over 32 blocks (thread == bin)
        int run = 0;
#pragma unroll
        for (int b = 0; b < 32; b++) {
            int v = hist[b * 256 + tid];
            hist[b * 256 + tid] = (unsigned short)run;
            run += v;
        }
        tot[tid] = run;
    }
    __syncthreads();
    {   // exclusive scan over 256 bins (all threads hit the barriers)
        int v = 0;
        if (tid < 256) { v = tot[tid]; bse[tid] = v; }
        __syncthreads();
        for (int d = 1; d < 256; d <<= 1) {
            int o = (tid >= d && tid < 256) ? bse[tid - d] : 0;
            __syncthreads();
            if (tid < 256) { v += o; bse[tid] = v; }
            __syncthreads();
        }
        if (tid < 256) {
            int e = (tid > 0) ? bse[tid - 1] : 0;
            __syncthreads();
            bse[tid] = e;
        } else __syncthreads();
    }
    __syncthreads();
#pragma unroll
    for (int bi = 0; bi < 2; bi++) {
        int b = wrp + bi * 16;
        int r = b * 32 + lane;
        int l = mylen[bi];
        perm[bse[l] + hist[b * 256 + l] + myintra[bi]] = (unsigned short)r;
    }
    __syncthreads();

    // ---------- slot assignment (dual schedule, makespan ~281) ----------
    int q = c + 152 * g;
    int nd = 0;
    int dls[4] = {0, 0, 0, 0};
    if (q < 232) { nd = 1; dls[0] = 511 - q; }
    else if (q - 232 < 70) {
        int sl = q - 232;
        nd = 4; dls[0] = sl; dls[1] = 139 - sl; dls[2] = 140 + sl; dls[3] = 279 - sl;
    }
    int rows[8], les[8];
#pragma unroll 1
    for (int k = 0; k < nd; k++) {
        int d = dls[k];
        int a = perm[2 * d], b = perm[2 * d + 1];
        rows[2*k] = a;  rows[2*k+1] = b;
        les[2*k] = lengths[a] - 1;  les[2*k+1] = lengths[b] - 1;
    }
    __syncthreads();            // perm reads done; raw reusable

    // ---------- P = emb @ W_ih^T into skewed shP ----------
    unsigned long long w[32];
    load_w2(W_ih, j2, kq, w);
#pragma unroll 1
    for (int vi = 0; vi < 30; vi++) {
        int v = g * 30 + vi;
        const ulonglong2* eq = reinterpret_cast<const ulonglong2*>(emb + v * HID) + kq * 8;
        float s0, s1;
        dot2(eq, w, s0, s1);
        s0 += __shfl_xor_sync(0xffffffffu, s0, 1); s0 += __shfl_xor_sync(0xffffffffu, s0, 2);
        s1 += __shfl_xor_sync(0xffffffffu, s1, 1); s1 += __shfl_xor_sync(0xffffffffu, s1, 2);
        if (kq < 2) shP[v * 132 + jskew] = (kq & 1) ? s1 : s0;
    }
    __syncthreads();

    // ---------- reload w <- W_hh ----------
    load_w2(W_hh, j2, kq, w);

    // ---------- duals: RNN recurrence + fused FC ----------
#pragma unroll 1
    for (int k = 0; k < nd; k++) {
        int r0 = rows[2*k], r1 = rows[2*k+1];
        int le0 = les[2*k], le1 = les[2*k+1];
        int L = le1 + 1;                      // perm ascending -> r1 longest

        asm volatile("bar.sync %0, 256;" :: "r"(g + 1) : "memory");
        stok[(2*g + 0) * T_SEQ + u] = (unsigned char)x[r0 * T_SEQ + u];
        stok[(2*g + 1) * T_SEQ + u] = (unsigned char)x[r1 * T_SEQ + u];
        if (kq < 2) {
            shH[g][0][0][stskew] = 0.0f;
            shH[g][1][0][stskew] = 0.0f;
        }
        asm volatile("bar.sync %0, 256;" :: "r"(g + 1) : "memory");

#pragma unroll 1
        for (int t = 0; t < L; t++) {
            int cur = t & 1, nxt = cur ^ 1;
#pragma unroll
            for (int s = 0; s < 2; s++) {
                int tok    = stok[(2*g + s) * T_SEQ + t];
                float base = shP[tok * 132 + jskew];
                const ulonglong2* hq =
                    reinterpret_cast<const ulonglong2*>(&shH[g][s][cur][kq * 36]);
                float s0, s1;
                dot2(hq, w, s0, s1);
                s0 += __shfl_xor_sync(0xffffffffu, s0, 1);
                s0 += __shfl_xor_sync(0xffffffffu, s0, 2);
                s1 += __shfl_xor_sync(0xffffffffu, s1, 1);
                s1 += __shfl_xor_sync(0xffffffffu, s1, 2);
                float h = tanh_fast(base + ((kq & 1) ? s1 : s0));
                if (kq < 2) {
                    shH[g][s][nxt][stskew] = h;
                    int lend = s ? le1 : le0;
                    if (t == lend) sret[(2*g + s) * HID + jown] = h;
                }
            }
            asm volatile("bar.sync %0, 256;" :: "r"(g + 1) : "memory");
        }

        // fused FC: out[r] = W_fc @ h_ret + b_fc (threads 0..59 of group)
        if (u < VOCABN) {
            const float* wf = W_fc + u * HID;
#pragma unroll
            for (int s = 0; s < 2; s++) {
                const float* hh = sret + (2*g + s) * HID;
                float acc = b_fc[u];
#pragma unroll 8
                for (int k2 = 0; k2 < HID; k2++) acc += wf[k2] * hh[k2];
                out[(size_t)rows[2*k + s] * VOCABN + u] = acc;
            }
        }
    }
}

// ---------------- launch ----------------
extern "C" void kernel_launch(void* const* d_in, const int* in_sizes, int n_in,
                              void* d_out, int out_size) {
    const int*   x       = (const int*)d_in[0];
    const int*   lengths = (const int*)d_in[1];
    const float* emb     = (const float*)d_in[2];
    const float* W_ih    = (const float*)d_in[3];
    const float* W_hh    = (const float*)d_in[4];
    const float* W_fc    = (const float*)d_in[5];
    const float* b_fc    = (const float*)d_in[6];
    float*       out     = (float*)d_out;

    rnn_all<<<NCTA, 512>>>(x, lengths, W_hh, emb, W_ih, W_fc, b_fc, out);
}

// round 12
// speedup vs baseline: 1.0855x; 1.0855x over previous
#include <cuda_runtime.h>
#include <cuda_bf16.h>

#define T_SEQ   256
#define HID     128
#define BATCH   1024
#define VOCABN  60
#define NCTA    152

#define FMA2(acc, a, b) \
    asm("fma.rn.f32x2 %0, %1, %2, %0;" : "+l"(acc) : "l"(a), "l"(b))
#define ADD2(dst, a, b) \
    asm("add.rn.f32x2 %0, %1, %2;" : "=l"(dst) : "l"(a), "l"(b))
#define UNPACK2(lo, hi, v) \
    asm("mov.b64 {%0,%1}, %2;" : "=f"(lo), "=f"(hi) : "l"(v))

__device__ __forceinline__ float tanh_fast(float z) {
    float e = __expf(2.0f * z);
    return 1.0f - __fdividef(2.0f, e + 1.0f);
}

// 4-output x 32-k register-blocked partial dot (R10-proven).
__device__ __forceinline__ void dot4(
    const ulonglong2* __restrict__ src, const unsigned long long* w,
    float& s0, float& s1, float& s2, float& s3)
{
    unsigned long long vv[16];
#pragma unroll
    for (int i = 0; i < 8; i++) { ulonglong2 t = src[i]; vv[2*i] = t.x; vv[2*i+1] = t.y; }
    unsigned long long A[8];
#pragma unroll
    for (int i = 0; i < 8; i++) A[i] = 0ull;
#pragma unroll
    for (int m = 0; m < 4; m++) {
        const unsigned long long* wm = w + m * 16;
#pragma unroll
        for (int i = 0; i < 16; i += 2) {
            FMA2(A[2*m],     wm[i],     vv[i]);
            FMA2(A[2*m + 1], wm[i + 1], vv[i + 1]);
        }
    }
    float lo, hi;
    ADD2(A[0], A[0], A[1]); UNPACK2(lo, hi, A[0]); s0 = lo + hi;
    ADD2(A[2], A[2], A[3]); UNPACK2(lo, hi, A[2]); s1 = lo + hi;
    ADD2(A[4], A[4], A[5]); UNPACK2(lo, hi, A[4]); s2 = lo + hi;
    ADD2(A[6], A[6], A[7]); UNPACK2(lo, hi, A[6]); s3 = lo + hi;
}

__device__ __forceinline__ float quad_reduce_sel(float s0, float s1, float s2, float s3, int kq) {
    s0 += __shfl_xor_sync(0xffffffffu, s0, 1); s0 += __shfl_xor_sync(0xffffffffu, s0, 2);
    s1 += __shfl_xor_sync(0xffffffffu, s1, 1); s1 += __shfl_xor_sync(0xffffffffu, s1, 2);
    s2 += __shfl_xor_sync(0xffffffffu, s2, 1); s2 += __shfl_xor_sync(0xffffffffu, s2, 2);
    s3 += __shfl_xor_sync(0xffffffffu, s3, 1); s3 += __shfl_xor_sync(0xffffffffu, s3, 2);
    return (kq & 2) ? ((kq & 1) ? s3 : s2) : ((kq & 1) ? s1 : s0);
}

__device__ __forceinline__ void load_wblock(
    const float* __restrict__ Wsrc, int j4, int kq, unsigned long long* w)
{
#pragma unroll
    for (int m = 0; m < 4; m++) {
        const ulonglong2* Wq =
            reinterpret_cast<const ulonglong2*>(Wsrc) + (size_t)(j4 + 32*m) * 32 + kq * 8;
#pragma unroll
        for (int i = 0; i < 8; i++) {
            ulonglong2 t = Wq[i];
            w[m*16 + 2*i]     = t.x;
            w[m*16 + 2*i + 1] = t.y;
        }
    }
}

// ============ single fused kernel: sort + P + RNN(alternating sets) + FC ============
// 152 CTAs x 256 threads (2 halves of 128, single __syncthreads per interval).
// CTA c owns rows desc[c+152k], k=0..6 (equal-work striding, ~870 row-steps each).
// 8 slots: slot k -> set k&1, half (k>>1)&1, local k>>2. Interval i advances set
// (i&1) at t=i>>1: each set's h feedback chain gets TWO intervals of slack, fully
// hidden behind the other set's compute. FC fused at retirement, flushed next
// interval. Deterministic counting sort -> identical perm in every CTA.
__global__ __launch_bounds__(256, 1) void rnn_all(
    const int* __restrict__ x, const int* __restrict__ lengths,
    const float* __restrict__ W_hh,
    const float* __restrict__ emb, const float* __restrict__ W_ih,
    const float* __restrict__ W_fc, const float* __restrict__ b_fc,
    float* __restrict__ out)
{
    __shared__ __align__(16) unsigned char raw[48128];
    float*          shP  = (float*)raw;                     // [60*128] skewed-in-block
    float*          shH  = (float*)(raw + 30720);           // [8][2][144]
    unsigned char*  stok = raw + 39936;                     // [8][256]
    float*          sret = (float*)(raw + 41984);           // [8][128]
    unsigned short* perm = (unsigned short*)(raw + 46080);  // [1024]
    // sort scratch aliased over shP region:
    unsigned short* hist = (unsigned short*)raw;            // [32][256]
    int*            tot  = (int*)(raw + 16384);             // [256]
    int*            bse  = (int*)(raw + 17408);             // [256]

    int tid  = threadIdx.x;
    int g    = tid >> 7;          // half 0/1
    int u    = tid & 127;
    int kq   = u & 3;
    int j4   = u >> 2;            // 0..31
    int jown = j4 + 32 * kq;
    int mycol = 32 * kq + ((j4 + 8 * kq) & 31);   // conflict-free shP column
    int lane = tid & 31;
    int wrp  = tid >> 5;          // 0..7
    int c    = blockIdx.x;

    // ---------- deterministic counting sort (no atomics) ----------
    for (int i = tid; i < 8192; i += 256) hist[i] = 0;
    __syncthreads();
    int myintra[4], mylen[4];
#pragma unroll
    for (int bi = 0; bi < 4; bi++) {
        int b = wrp + bi * 8;
        int r = b * 32 + lane;
        int l = lengths[r] - 1;
        unsigned mask = __match_any_sync(0xffffffffu, l);
        int intra = __popc(mask & ((1u << lane) - 1u));
        if (intra == 0) hist[b * 256 + l] = (unsigned short)__popc(mask);
        myintra[bi] = intra; mylen[bi] = l;
    }
    __syncthreads();
    {   // per-bin serial scan over 32 blocks (thread == bin)
        int run = 0;
#pragma unroll
        for (int b = 0; b < 32; b++) {
            int v = hist[b * 256 + tid];
            hist[b * 256 + tid] = (unsigned short)run;
            run += v;
        }
        tot[tid] = run;
    }
    __syncthreads();
    {   // exclusive scan over 256 bins
        int v = tot[tid];
        bse[tid] = v;
        __syncthreads();
        for (int d = 1; d < 256; d <<= 1) {
            int o = (tid >= d) ? bse[tid - d] : 0;
            __syncthreads();
            v += o; bse[tid] = v;
            __syncthreads();
        }
        int e = (tid > 0) ? bse[tid - 1] : 0;
        __syncthreads();
        bse[tid] = e;
    }
    __syncthreads();
#pragma unroll
    for (int bi = 0; bi < 4; bi++) {
        int b = wrp + bi * 8;
        int r = b * 32 + lane;
        int l = mylen[bi];
        perm[bse[l] + hist[b * 256 + l] + myintra[bi]] = (unsigned short)r;
    }
    __syncthreads();

    // ---------- slot setup: rows desc[c + 152k], k = 0..7 (k=7 always empty) ----------
    int rowk[8], lendk[8];
    int lmax = 0;
#pragma unroll
    for (int k = 0; k < 8; k++) {
        int di = c + 152 * k;
        if (di < BATCH) {
            int r = perm[BATCH - 1 - di];
            rowk[k]  = r;
            lendk[k] = lengths[r] - 1;
        } else { rowk[k] = 0; lendk[k] = -1; }
        lmax = max(lmax, lendk[k] + 1);
    }
    __syncthreads();                 // perm reads done; shP region reusable

    // tokens + h init (each half serves its own 4 slots: k = 2g + {0,1,4,5})
#pragma unroll
    for (int e = 0; e < 4; e++) {
        int k = 2 * g + ((e & 1) ? 1 : 0) + ((e & 2) ? 4 : 0);
        if (lendk[k] >= 0) {
            stok[k * T_SEQ + u]       = (unsigned char)x[rowk[k] * T_SEQ + u];
            stok[k * T_SEQ + u + 128] = (unsigned char)x[rowk[k] * T_SEQ + u + 128];
        }
        shH[(k * 2 + 0) * 144 + kq * 36 + j4] = 0.0f;
        shH[(k * 2 + 1) * 144 + kq * 36 + j4] = 0.0f;
    }

    // ---------- P = emb @ W_ih^T ----------
    unsigned long long w[64];
    load_wblock(W_ih, j4, kq, w);
#pragma unroll 1
    for (int vi = 0; vi < 30; vi++) {
        int v = g * 30 + vi;
        const ulonglong2* eq = reinterpret_cast<const ulonglong2*>(emb + v * HID) + kq * 8;
        float s0, s1, s2, s3;
        dot4(eq, w, s0, s1, s2, s3);
        shP[v * HID + mycol] = quad_reduce_sel(s0, s1, s2, s3, kq);
    }
    load_wblock(W_hh, j4, kq, w);
    __syncthreads();

    // ---------- alternating-set interval loop ----------
    int fc_now = 0, fc_next = 0;
    int imax = 2 * lmax + 2;
#pragma unroll 1
    for (int i = 0; i < imax; i++) {
        int set = i & 1, t = i >> 1;
#pragma unroll
        for (int s = 0; s < 2; s++) {
            int k = set + 2 * g + 4 * s;          // this half's slot of this set
            if (t <= lendk[k]) {
                int tok    = stok[k * T_SEQ + t];
                float base = shP[tok * HID + mycol];
                const ulonglong2* hq = reinterpret_cast<const ulonglong2*>(
                    &shH[(k * 2 + (t & 1)) * 144 + kq * 36]);
                float s0, s1, s2, s3;
                dot4(hq, w, s0, s1, s2, s3);
                float h = tanh_fast(base + quad_reduce_sel(s0, s1, s2, s3, kq));
                shH[(k * 2 + ((t & 1) ^ 1)) * 144 + kq * 36 + j4] = h;
                if (t == lendk[k]) {
                    sret[k * HID + jown] = h;
                    fc_next |= 1 << k;
                }
            }
        }
        // flush FCs pended last interval (sret crossed one barrier)
        if (fc_now && u < VOCABN) {
            const float* wf = W_fc + u * HID;
#pragma unroll 1
            for (int k = 2 * g; k < 8; k++) {
                if ((fc_now >> k) & 1) {
                    const float* hh = sret + k * HID;
                    float acc = b_fc[u];
#pragma unroll 8
                    for (int k2 = 0; k2 < HID; k2++) acc += wf[k2] * hh[k2];
                    out[(size_t)rowk[k] * VOCABN + u] = acc;
                }
            }
        }
        __syncthreads();
        fc_now = fc_next; fc_next = 0;
    }
    // final flush
    if (fc_now && u < VOCABN) {
        const float* wf = W_fc + u * HID;
#pragma unroll 1
        for (int k = 2 * g; k < 8; k++) {
            if ((fc_now >> k) & 1) {
                const float* hh = sret + k * HID;
                float acc = b_fc[u];
#pragma unroll 8
                for (int k2 = 0; k2 < HID; k2++) acc += wf[k2] * hh[k2];
                out[(size_t)rowk[k] * VOCABN + u] = acc;
            }
        }
    }
}

// ---------------- launch ----------------
extern "C" void kernel_launch(void* const* d_in, const int* in_sizes, int n_in,
                              void* d_out, int out_size) {
    const int*   x       = (const int*)d_in[0];
    const int*   lengths = (const int*)d_in[1];
    const float* emb     = (const float*)d_in[2];
    const float* W_ih    = (const float*)d_in[3];
    const float* W_hh    = (const float*)d_in[4];
    const float* W_fc    = (const float*)d_in[5];
    const float* b_fc    = (const float*)d_in[6];
    float*       out     = (float*)d_out;

    rnn_all<<<NCTA, 256>>>(x, lengths, W_hh, emb, W_ih, W_fc, b_fc, out);
}

// round 13
// speedup vs baseline: 1.4296x; 1.3171x over previous
#include <cuda_runtime.h>
#include <cuda_bf16.h>

#define T_SEQ   256
#define HID     128
#define BATCH   1024
#define VOCABN  60
#define NCTA    152

#define FMA2(acc, a, b) \
    asm("fma.rn.f32x2 %0, %1, %2, %0;" : "+l"(acc) : "l"(a), "l"(b))
#define ADD2(dst, a, b) \
    asm("add.rn.f32x2 %0, %1, %2;" : "=l"(dst) : "l"(a), "l"(b))
#define UNPACK2(lo, hi, v) \
    asm("mov.b64 {%0,%1}, %2;" : "=f"(lo), "=f"(hi) : "l"(v))

__device__ __forceinline__ float tanh_fast(float z) {
    float e = __expf(2.0f * z);
    return 1.0f - __fdividef(2.0f, e + 1.0f);
}

// ============ single fused kernel: sort + P + RNN(dual schedule) + FC ============
// 152 CTAs x 256 threads = 2 independent groups of 128 (per-group named barrier).
// R3-proven body: thread j holds W row j as 64 packed f32x2 regs; h via broadcast
// LDS.128; 64 FFMA2/slot; NO shfl. Work unit = dual of sorted-adjacent rows
// (waste <1%); closed-form balanced dual lists over 512 desc duals.
__global__ __launch_bounds__(256, 1) void rnn_all(
    const int* __restrict__ x, const int* __restrict__ lengths,
    const float* __restrict__ W_hh,
    const float* __restrict__ emb, const float* __restrict__ W_ih,
    const float* __restrict__ W_fc, const float* __restrict__ b_fc,
    float* __restrict__ out)
{
    __shared__ __align__(16) unsigned char raw[30720];       // sort scratch, then shP
    __shared__ __align__(16) float sh_h[2][2][2][HID];       // 4 KB double-buffered h
    __shared__ unsigned char stok[2][2][T_SEQ];              // 1 KB tokens (u8)
    __shared__ float sret[2][2][HID];                        // 2 KB retired h
    __shared__ unsigned short perm[BATCH];                   // 2 KB (survives)

    float*          shP  = (float*)raw;                     // [60*128]
    unsigned short* hist = (unsigned short*)raw;            // [32][256] u16
    int*            tot  = (int*)(raw + 16384);             // [256]
    int*            bse  = (int*)(raw + 17408);             // [256]

    int tid  = threadIdx.x;
    int g    = tid >> 7;          // group 0/1
    int j    = tid & 127;
    int lane = tid & 31;
    int wrp  = tid >> 5;          // 0..7
    int c    = blockIdx.x;

    // ---------- deterministic counting sort (match/popc, no atomics) ----------
    for (int i = tid; i < 8192; i += 256) hist[i] = 0;
    __syncthreads();
    int myintra[4], mylen[4];
#pragma unroll
    for (int bi = 0; bi < 4; bi++) {
        int b = wrp + bi * 8;
        int r = b * 32 + lane;
        int l = lengths[r] - 1;
        unsigned mask = __match_any_sync(0xffffffffu, l);
        int intra = __popc(mask & ((1u << lane) - 1u));
        if (intra == 0) hist[b * 256 + l] = (unsigned short)__popc(mask);
        myintra[bi] = intra; mylen[bi] = l;
    }
    __syncthreads();
    {   // per-bin serial scan over 32 blocks (thread == bin)
        int run = 0;
#pragma unroll
        for (int b = 0; b < 32; b++) {
            int v = hist[b * 256 + tid];
            hist[b * 256 + tid] = (unsigned short)run;
            run += v;
        }
        tot[tid] = run;
    }
    __syncthreads();
    {   // exclusive scan over 256 bins
        int v = tot[tid];
        bse[tid] = v;
        __syncthreads();
        for (int d = 1; d < 256; d <<= 1) {
            int o = (tid >= d) ? bse[tid - d] : 0;
            __syncthreads();
            v += o; bse[tid] = v;
            __syncthreads();
        }
        int e = (tid > 0) ? bse[tid - 1] : 0;
        __syncthreads();
        bse[tid] = e;
    }
    __syncthreads();
#pragma unroll
    for (int bi = 0; bi < 4; bi++) {
        int b = wrp + bi * 8;
        int r = b * 32 + lane;
        int l = mylen[bi];
        perm[bse[l] + hist[b * 256 + l] + myintra[bi]] = (unsigned short)r;
    }
    __syncthreads();

    // ---------- stage emb, compute P = emb @ W_ih^T in place (R3 2-wave) ----------
    for (int i = tid; i < VOCABN * HID; i += 256) shP[i] = emb[i];
    unsigned long long w[64];
    {
        const ulonglong2* Wq = reinterpret_cast<const ulonglong2*>(W_ih) + (size_t)j * 32;
#pragma unroll
        for (int i = 0; i < 32; i++) { ulonglong2 tq = Wq[i]; w[2*i] = tq.x; w[2*i+1] = tq.y; }
    }
    __syncthreads();
#pragma unroll 1
    for (int wave = 0; wave < 2; wave++) {
        float pv[15];
        int v0 = g * 30 + wave * 15;
#pragma unroll 1
        for (int vi = 0; vi < 15; vi++) {
            const ulonglong2* eq = reinterpret_cast<const ulonglong2*>(&shP[(v0 + vi) * HID]);
            unsigned long long a0 = 0ull, a1 = 0ull, a2 = 0ull, a3 = 0ull;
#pragma unroll
            for (int i = 0; i < 32; i += 2) {
                ulonglong2 e0 = eq[i];
                ulonglong2 e1 = eq[i + 1];
                FMA2(a0, w[2*i + 0], e0.x);
                FMA2(a1, w[2*i + 1], e0.y);
                FMA2(a2, w[2*i + 2], e1.x);
                FMA2(a3, w[2*i + 3], e1.y);
            }
            ADD2(a0, a0, a1); ADD2(a2, a2, a3); ADD2(a0, a0, a2);
            float lo, hi; UNPACK2(lo, hi, a0);
            pv[vi] = lo + hi;
        }
        __syncthreads();
#pragma unroll
        for (int vi = 0; vi < 15; vi++) shP[(v0 + vi) * HID + j] = pv[vi];
        __syncthreads();
    }
    // reload w <- W_hh row j
    {
        const ulonglong2* Wq = reinterpret_cast<const ulonglong2*>(W_hh) + (size_t)j * 32;
#pragma unroll
        for (int i = 0; i < 32; i++) { ulonglong2 tq = Wq[i]; w[2*i] = tq.x; w[2*i+1] = tq.y; }
    }

    // ---------- balanced dual lists (desc duals d=0..511; dual d = rows
    // perm[1023-2d], perm[1022-2d]; lens descending). Coverage: {c}, {303-c},
    // {455-c}, {607-c (c>=96)} = each dual exactly once. ----------
    int list[2], n;
    if (g == 0) { list[0] = c;       list[1] = 607 - c; n = (c >= 96) ? 2 : 1; }
    else        { list[0] = 303 - c; list[1] = 455 - c; n = 2; }

#pragma unroll 1
    for (int it = 0; it < n; it++) {
        int d  = list[it];
        int r0 = perm[1023 - 2 * d];          // longer row of the dual
        int r1 = perm[1022 - 2 * d];
        int le0 = lengths[r0] - 1;
        int le1 = lengths[r1] - 1;
        int L = le0 + 1;                       // r0 is the max

        asm volatile("bar.sync %0, 128;" :: "r"(g + 1) : "memory");
        stok[g][0][j]       = (unsigned char)x[r0 * T_SEQ + j];
        stok[g][0][j + 128] = (unsigned char)x[r0 * T_SEQ + j + 128];
        stok[g][1][j]       = (unsigned char)x[r1 * T_SEQ + j];
        stok[g][1][j + 128] = (unsigned char)x[r1 * T_SEQ + j + 128];
        sh_h[g][0][0][j] = 0.0f;
        sh_h[g][1][0][j] = 0.0f;
        asm volatile("bar.sync %0, 128;" :: "r"(g + 1) : "memory");

#pragma unroll 1
        for (int t = 0; t < L; t++) {
            int cur = t & 1, nxt = cur ^ 1;
#pragma unroll
            for (int s = 0; s < 2; s++) {
                int tok    = stok[g][s][t];
                float base = shP[tok * HID + j];
                const ulonglong2* hq =
                    reinterpret_cast<const ulonglong2*>(sh_h[g][s][cur]);
                unsigned long long a0 = 0ull, a1 = 0ull, a2 = 0ull, a3 = 0ull;
#pragma unroll
                for (int i = 0; i < 32; i += 2) {     // 16 LDS.128 + 32... x2 = R3 body
                    ulonglong2 v0 = hq[i];
                    ulonglong2 v1 = hq[i + 1];
                    FMA2(a0, w[2*i + 0], v0.x);
                    FMA2(a1, w[2*i + 1], v0.y);
                    FMA2(a2, w[2*i + 2], v1.x);
                    FMA2(a3, w[2*i + 3], v1.y);
                }
                ADD2(a0, a0, a1); ADD2(a2, a2, a3); ADD2(a0, a0, a2);
                float lo, hi; UNPACK2(lo, hi, a0);
                float h = tanh_fast(base + lo + hi);
                sh_h[g][s][nxt][j] = h;
                int lend = s ? le1 : le0;
                if (t == lend) sret[g][s][j] = h;      // retire (predicated STS)
            }
            asm volatile("bar.sync %0, 128;" :: "r"(g + 1) : "memory");
        }

        // fused FC for both retired rows (sret visible after last loop barrier)
        if (j < VOCABN) {
            const float* wf = W_fc + j * HID;
            float acc0 = b_fc[j], acc1 = acc0;
#pragma unroll 8
            for (int k2 = 0; k2 < HID; k2++) {
                float wv = wf[k2];
                acc0 += wv * sret[g][0][k2];
                acc1 += wv * sret[g][1][k2];
            }
            out[(size_t)r0 * VOCABN + j] = acc0;
            out[(size_t)r1 * VOCABN + j] = acc1;
        }
    }
}

// ---------------- launch ----------------
extern "C" void kernel_launch(void* const* d_in, const int* in_sizes, int n_in,
                              void* d_out, int out_size) {
    const int*   x       = (const int*)d_in[0];
    const int*   lengths = (const int*)d_in[1];
    const float* emb     = (const float*)d_in[2];
    const float* W_ih    = (const float*)d_in[3];
    const float* W_hh    = (const float*)d_in[4];
    const float* W_fc    = (const float*)d_in[5];
    const float* b_fc    = (const float*)d_in[6];
    float*       out     = (float*)d_out;

    rnn_all<<<NCTA, 256>>>(x, lengths, W_hh, emb, W_ih, W_fc, b_fc, out);
}